// round 5
// baseline (speedup 1.0000x reference)
#include <cuda_runtime.h>

#define SCALE 0.125f

// ---------------- scratch (device globals: allocation-free) ----------------
__device__ float g_ep[134217728];    // exp(SCALE*q.k)  (2,16,2048,2048) 536.9 MB
__device__ float g_qkv[12582912];    // (2,2048,3072)  50.3 MB
__device__ float g_zinv[8388608];    // (2,2048,2048)  33.5 MB
__device__ float g_wavg[4194304];    // (2,2048,1024)  16.8 MB

// ---------------- f32x2 packed-FMA helpers ----------------
__device__ __forceinline__ unsigned long long pack2(float lo, float hi) {
    unsigned long long r;
    asm("mov.b64 %0, {%1, %2};" : "=l"(r) : "f"(lo), "f"(hi));
    return r;
}
__device__ __forceinline__ float2 unpack2(unsigned long long v) {
    float2 r;
    asm("mov.b64 {%0, %1}, %2;" : "=f"(r.x), "=f"(r.y) : "l"(v));
    return r;
}
__device__ __forceinline__ void fma2(unsigned long long& c, unsigned long long a, unsigned long long b) {
    asm("fma.rn.f32x2 %0, %1, %2, %3;" : "=l"(c) : "l"(a), "l"(b), "l"(c));
}

// ---------------- FMA-pipe exp (no MUFU) ----------------
// Valid for |x| < 80 (covers dp ~ N(0,1) with absurd margin).
// t = x*log2e; i = rint(t); y = x - i*ln2; exp(x) = 2^i * e^y via 5-term
// Taylor (|y|<=0.347 -> rel err ~2.4e-6). 2^i by exponent-field add.
__device__ __forceinline__ float fexp(float x) {
    float t = x * 1.44269504088896340736f;
    float i = rintf(t);
    float y = fmaf(-i, 0.69314718055994530942f, x);
    float p = 8.3333337680e-3f;                        // 1/120
    p = fmaf(p, y, 4.1666668654e-2f);                  // 1/24
    p = fmaf(p, y, 1.6666667163e-1f);                  // 1/6
    p = fmaf(p, y, 5.0000000000e-1f);
    p = fmaf(p, y, 1.0f);
    p = fmaf(p, y, 1.0f);
    return __int_as_float(__float_as_int(p) + (((int)i) << 23));
}

// ======================================================================
// Generic NN GEMM with bias: C[M,N] = A[M,K] @ B[K,N] + bias[N]
// BM=128, BN=128, BK=16, 256 threads, 8x8 microtile via f32x2, occ 2.
// ======================================================================
__global__ __launch_bounds__(256, 2)
void gemm_nn_bias(const float* __restrict__ A, const float* __restrict__ Bm,
                  const float* __restrict__ bias, float* __restrict__ C,
                  int M, int N, int K)
{
    __shared__ float As[16][136];   // [k][m], pad 136 -> conflict-free stores
    __shared__ float Bs[16][128];   // [k][n]
    const int tid = threadIdx.x;
    const int bm = blockIdx.y << 7;
    const int bn = blockIdx.x << 7;
    const int tx = tid & 15, ty = tid >> 4;

    unsigned long long acc[8][4];
#pragma unroll
    for (int i = 0; i < 8; i++)
#pragma unroll
        for (int j = 0; j < 4; j++) acc[i][j] = 0ull;

    const float* Ab = A + (size_t)bm * K;
    const float* Bb = Bm + bn;

    for (int k0 = 0; k0 < K; k0 += 16) {
#pragma unroll
        for (int i = 0; i < 2; i++) {              // A tile: 128x16 (transpose)
            int idx = i * 256 + tid;
            int row = idx >> 2, seg = idx & 3;
            float4 v = *(const float4*)(Ab + (size_t)row * K + (k0 + seg * 4));
            As[seg*4+0][row] = v.x;
            As[seg*4+1][row] = v.y;
            As[seg*4+2][row] = v.z;
            As[seg*4+3][row] = v.w;
        }
#pragma unroll
        for (int i = 0; i < 2; i++) {              // B tile: 16x128
            int idx = i * 256 + tid;
            int r = idx >> 5, c = (idx & 31) << 2;
            *(float4*)&Bs[r][c] = *(const float4*)(Bb + (size_t)(k0 + r) * N + c);
        }
        __syncthreads();
#pragma unroll
        for (int kk = 0; kk < 16; kk++) {
            float4 a0 = *(const float4*)&As[kk][ty*8];
            float4 a1 = *(const float4*)&As[kk][ty*8+4];
            float4 b0 = *(const float4*)&Bs[kk][tx*8];
            float4 b1 = *(const float4*)&Bs[kk][tx*8+4];
            unsigned long long bp[4] = {pack2(b0.x,b0.y), pack2(b0.z,b0.w),
                                        pack2(b1.x,b1.y), pack2(b1.z,b1.w)};
            float av[8] = {a0.x,a0.y,a0.z,a0.w,a1.x,a1.y,a1.z,a1.w};
#pragma unroll
            for (int i = 0; i < 8; i++) {
                unsigned long long ap = pack2(av[i], av[i]);
#pragma unroll
                for (int j = 0; j < 4; j++) fma2(acc[i][j], ap, bp[j]);
            }
        }
        __syncthreads();
    }
#pragma unroll
    for (int i = 0; i < 8; i++) {
        int row = bm + ty*8 + i;
#pragma unroll
        for (int j = 0; j < 4; j++) {
            float2 v = unpack2(acc[i][j]);
            int col = bn + tx*8 + j*2;
            float2 o = make_float2(v.x + bias[col], v.y + bias[col+1]);
            *(float2*)&C[(size_t)row * N + col] = o;
        }
    }
}

// ======================================================================
// Batched NT GEMM + fused FMA-pipe exp epilogue:
// ep[z][q][k] = exp(SCALE * Q_z[q,:] . K_z[k,:])   (Kdim=64)
// z = b*16+h. Q row q at qkv[b*6291456 + q*3072 + h*64], K at +1024.
// ep stored with .cs (streaming): single-pass producer, keep L2 clean.
// ======================================================================
__global__ __launch_bounds__(256, 2)
void gemm_qk_exp(const float* __restrict__ qkv, float* __restrict__ ep)
{
    __shared__ float As[16][136];
    __shared__ float Bs[16][136];
    const int tid = threadIdx.x;
    const int z = blockIdx.z;
    const int b = z >> 4, h = z & 15;
    const int bm = blockIdx.y << 7, bn = blockIdx.x << 7;
    const int tx = tid & 15, ty = tid >> 4;

    const float* Aq = qkv + (size_t)b * 6291456 + h * 64;           // Q
    const float* Bk = qkv + (size_t)b * 6291456 + 1024 + h * 64;    // K
    float* C = ep + (size_t)z * 4194304;

    unsigned long long acc[8][4];
#pragma unroll
    for (int i = 0; i < 8; i++)
#pragma unroll
        for (int j = 0; j < 4; j++) acc[i][j] = 0ull;

    for (int k0 = 0; k0 < 64; k0 += 16) {
#pragma unroll
        for (int i = 0; i < 2; i++) {
            int idx = i * 256 + tid;
            int row = idx >> 2, seg = idx & 3;
            float4 v = *(const float4*)(Aq + (size_t)(bm + row) * 3072 + k0 + seg * 4);
            As[seg*4+0][row] = v.x;
            As[seg*4+1][row] = v.y;
            As[seg*4+2][row] = v.z;
            As[seg*4+3][row] = v.w;
            float4 w = *(const float4*)(Bk + (size_t)(bn + row) * 3072 + k0 + seg * 4);
            Bs[seg*4+0][row] = w.x;
            Bs[seg*4+1][row] = w.y;
            Bs[seg*4+2][row] = w.z;
            Bs[seg*4+3][row] = w.w;
        }
        __syncthreads();
#pragma unroll
        for (int kk = 0; kk < 16; kk++) {
            float4 a0 = *(const float4*)&As[kk][ty*8];
            float4 a1 = *(const float4*)&As[kk][ty*8+4];
            float4 b0 = *(const float4*)&Bs[kk][tx*8];
            float4 b1 = *(const float4*)&Bs[kk][tx*8+4];
            unsigned long long bp[4] = {pack2(b0.x,b0.y), pack2(b0.z,b0.w),
                                        pack2(b1.x,b1.y), pack2(b1.z,b1.w)};
            float av[8] = {a0.x,a0.y,a0.z,a0.w,a1.x,a1.y,a1.z,a1.w};
#pragma unroll
            for (int i = 0; i < 8; i++) {
                unsigned long long ap = pack2(av[i], av[i]);
#pragma unroll
                for (int j = 0; j < 4; j++) fma2(acc[i][j], ap, bp[j]);
            }
        }
        __syncthreads();
    }
#pragma unroll
    for (int i = 0; i < 8; i++) {
        int row = bm + ty*8 + i;
#pragma unroll
        for (int j = 0; j < 4; j++) {
            float2 v = unpack2(acc[i][j]);
            int col = bn + tx*8 + j*2;
            float2 o = make_float2(fexp(v.x * SCALE), fexp(v.y * SCALE));
            __stcs((float2*)&C[(size_t)row * 2048 + col], o);
        }
    }
}

// ======================================================================
// zinv[b,q,k] = 1 / sum_h ep[b,h,q,k]   (softmax over HEADS axis)
// float4 per thread: 16 strided LDG.128, MLP=16, streaming loads.
// ======================================================================
__global__ __launch_bounds__(256)
void softmax_z(const float* __restrict__ ep, float* __restrict__ zinv)
{
    size_t i4 = (size_t)blockIdx.x * 256 + threadIdx.x;  // over 2*2048*2048/4
    size_t b = i4 >> 20;                                  // 1048576 float4 per b
    size_t qk4 = i4 & 1048575;
    const float4* p = (const float4*)(ep + (b << 26)) + qk4;
    float4 s = make_float4(0.f, 0.f, 0.f, 0.f);
#pragma unroll
    for (int h = 0; h < 16; h++) {
        float4 v = __ldcs(p + ((size_t)h << 20));         // stride 2048*2048/4 float4
        s.x += v.x; s.y += v.y; s.z += v.z; s.w += v.w;
    }
    float4 o = make_float4(1.f/s.x, 1.f/s.y, 1.f/s.z, 1.f/s.w);
    *((float4*)zinv + i4) = o;
}

// ======================================================================
// Batched NN GEMM with normalization on A:
// wavg[b,q,h*64+d] = sum_k (ep[z,q,k]*zinv[b,q,k]) * V[b,k,h,d]
// BM=128, BN=64, BK=16, 256 threads, 8x4 microtile.
// ep read streaming (.cs); zinv/V keep default policy (real L2 reuse).
// ======================================================================
__global__ __launch_bounds__(256, 2)
void gemm_pv(const float* __restrict__ ep, const float* __restrict__ zinv,
             const float* __restrict__ qkv, float* __restrict__ wavg)
{
    __shared__ float As[16][136];
    __shared__ float Bs[16][64];
    const int tid = threadIdx.x;
    const int z = blockIdx.z, b = z >> 4, h = z & 15;
    const int bm = blockIdx.y << 7;
    const int tx = tid & 15, ty = tid >> 4;

    const float* A  = ep + (size_t)z * 4194304 + (size_t)bm * 2048;
    const float* Zi = zinv + (size_t)b * 4194304 + (size_t)bm * 2048;
    const float* Bv = qkv + (size_t)b * 6291456 + 2048 + h * 64;
    float* C = wavg + (size_t)b * 2097152 + h * 64;

    unsigned long long acc[8][2];
#pragma unroll
    for (int i = 0; i < 8; i++) { acc[i][0] = 0ull; acc[i][1] = 0ull; }

    for (int k0 = 0; k0 < 2048; k0 += 16) {
#pragma unroll
        for (int i = 0; i < 2; i++) {              // A tile: attn = ep * zinv
            int idx = i * 256 + tid;
            int row = idx >> 2, seg = idx & 3;
            size_t off = (size_t)row * 2048 + k0 + seg * 4;
            float4 a  = __ldcs((const float4*)(A + off));
            float4 zi = *(const float4*)(Zi + off);
            As[seg*4+0][row] = a.x * zi.x;
            As[seg*4+1][row] = a.y * zi.y;
            As[seg*4+2][row] = a.z * zi.z;
            As[seg*4+3][row] = a.w * zi.w;
        }
        {                                           // V tile: 16x64
            int r = tid >> 4, c = (tid & 15) << 2;
            *(float4*)&Bs[r][c] = *(const float4*)(Bv + (size_t)(k0 + r) * 3072 + c);
        }
        __syncthreads();
#pragma unroll
        for (int kk = 0; kk < 16; kk++) {
            float4 a0 = *(const float4*)&As[kk][ty*8];
            float4 a1 = *(const float4*)&As[kk][ty*8+4];
            float4 b0 = *(const float4*)&Bs[kk][tx*4];
            unsigned long long bp[2] = {pack2(b0.x,b0.y), pack2(b0.z,b0.w)};
            float av[8] = {a0.x,a0.y,a0.z,a0.w,a1.x,a1.y,a1.z,a1.w};
#pragma unroll
            for (int i = 0; i < 8; i++) {
                unsigned long long ap = pack2(av[i], av[i]);
                fma2(acc[i][0], ap, bp[0]);
                fma2(acc[i][1], ap, bp[1]);
            }
        }
        __syncthreads();
    }
#pragma unroll
    for (int i = 0; i < 8; i++) {
        int row = bm + ty*8 + i;
#pragma unroll
        for (int j = 0; j < 2; j++) {
            float2 v = unpack2(acc[i][j]);
            *(float2*)&C[(size_t)row * 1024 + tx*4 + j*2] = v;
        }
    }
}

// ======================================================================
extern "C" void kernel_launch(void* const* d_in, const int* in_sizes, int n_in,
                              void* d_out, int out_size)
{
    const float* x      = (const float*)d_in[0];   // (2,2048,1024)
    const float* w_qkv  = (const float*)d_in[1];   // (1024,3072)
    const float* b_qkv  = (const float*)d_in[2];   // (3072,)
    const float* w_proj = (const float*)d_in[3];   // (1024,1024)
    const float* b_proj = (const float*)d_in[4];   // (1024,)
    float* out = (float*)d_out;                    // (2,2048,1024)

    float *qkv, *ep, *zinv, *wavg;
    cudaGetSymbolAddress((void**)&qkv,  g_qkv);
    cudaGetSymbolAddress((void**)&ep,   g_ep);
    cudaGetSymbolAddress((void**)&zinv, g_zinv);
    cudaGetSymbolAddress((void**)&wavg, g_wavg);

    // 1) qkv = x @ w_qkv + b_qkv          (M=4096, N=3072, K=1024)
    gemm_nn_bias<<<dim3(24, 32), 256>>>(x, w_qkv, b_qkv, qkv, 4096, 3072, 1024);
    // 2) ep[b,h,q,k] = exp(SCALE * q.k)   (32 batches of 2048x2048x64, FMA-exp fused)
    gemm_qk_exp<<<dim3(16, 16, 32), 256>>>(qkv, ep);
    // 3) zinv = 1 / sum_h ep              (softmax denominator over heads)
    softmax_z<<<8192, 256>>>(ep, zinv);
    // 4) wavg = (ep*zinv) @ V             (32 batches of 2048x64x2048)
    gemm_pv<<<dim3(1, 16, 32), 256>>>(ep, zinv, qkv, wavg);
    // 5) out = wavg @ w_proj + b_proj     (M=4096, N=1024, K=1024)
    gemm_nn_bias<<<dim3(8, 32), 256>>>(wavg, w_proj, b_proj, out, 4096, 1024, 1024);
}

// round 6
// speedup vs baseline: 1.0530x; 1.0530x over previous
#include <cuda_runtime.h>

#define SCALE 0.125f

// ---------------- scratch (device globals: allocation-free) ----------------
__device__ float g_ep[134217728];    // exp(SCALE*q.k)  (2,16,2048,2048) 536.9 MB
__device__ float g_qkv[12582912];    // (2,2048,3072)  50.3 MB
__device__ float g_zinv[8388608];    // (2,2048,2048)  33.5 MB
__device__ float g_wavg[4194304];    // (2,2048,1024)  16.8 MB

// ---------------- f32x2 packed-FMA helpers ----------------
__device__ __forceinline__ unsigned long long pack2(float lo, float hi) {
    unsigned long long r;
    asm("mov.b64 %0, {%1, %2};" : "=l"(r) : "f"(lo), "f"(hi));
    return r;
}
__device__ __forceinline__ float2 unpack2(unsigned long long v) {
    float2 r;
    asm("mov.b64 {%0, %1}, %2;" : "=f"(r.x), "=f"(r.y) : "l"(v));
    return r;
}
__device__ __forceinline__ void fma2(unsigned long long& c, unsigned long long a, unsigned long long b) {
    asm("fma.rn.f32x2 %0, %1, %2, %3;" : "=l"(c) : "l"(a), "l"(b), "l"(c));
}

// ---------------- FMA-pipe exp (no MUFU) ----------------
__device__ __forceinline__ float fexp(float x) {
    float t = x * 1.44269504088896340736f;
    float i = rintf(t);
    float y = fmaf(-i, 0.69314718055994530942f, x);
    float p = 8.3333337680e-3f;                        // 1/120
    p = fmaf(p, y, 4.1666668654e-2f);                  // 1/24
    p = fmaf(p, y, 1.6666667163e-1f);                  // 1/6
    p = fmaf(p, y, 5.0000000000e-1f);
    p = fmaf(p, y, 1.0f);
    p = fmaf(p, y, 1.0f);
    return __int_as_float(__float_as_int(p) + (((int)i) << 23));
}

// ======================================================================
// Generic NN GEMM with bias, 2-stage pipelined:
// C[M,N] = A[M,K] @ B[K,N] + bias[N]
// BM=128, BN=128, BK=16, 256 threads, 8x8 microtile via f32x2, occ 2.
// ======================================================================
__global__ __launch_bounds__(256, 2)
void gemm_nn_bias(const float* __restrict__ A, const float* __restrict__ Bm,
                  const float* __restrict__ bias, float* __restrict__ C,
                  int M, int N, int K)
{
    __shared__ float As[2][16][136];
    __shared__ float Bs[2][16][128];
    const int tid = threadIdx.x;
    const int bm = blockIdx.y << 7;
    const int bn = blockIdx.x << 7;
    const int tx = tid & 15, ty = tid >> 4;

    // per-thread fill coordinates (2 float4 each for A and B)
    const int ar0 = tid >> 1,        as0 = (tid & 1) * 2;       // idx = tid*2?? no:
    // A tile fill: idx in [0,512): row=idx>>2, seg=idx&3 ; thread covers idx=tid and tid+256
    const int arow0 = tid >> 2,        aseg0 = tid & 3;
    const int arow1 = (tid + 256) >> 2, aseg1 = tid & 3;
    // B tile fill: idx in [0,512): r=idx>>5, c=(idx&31)*4 ; thread covers tid and tid+256
    const int br0 = tid >> 5,          bc0 = (tid & 31) << 2;
    const int br1 = (tid + 256) >> 5,  bc1 = (tid & 31) << 2;
    (void)ar0; (void)as0;

    unsigned long long acc[8][4];
#pragma unroll
    for (int i = 0; i < 8; i++)
#pragma unroll
        for (int j = 0; j < 4; j++) acc[i][j] = 0ull;

    const float* Ab = A + (size_t)bm * K;
    const float* Bb = Bm + bn;

    // ---- prologue: tile 0 straight to smem[0] ----
    {
        float4 va0 = *(const float4*)(Ab + (size_t)arow0 * K + aseg0 * 4);
        float4 va1 = *(const float4*)(Ab + (size_t)arow1 * K + aseg1 * 4);
        float4 vb0 = *(const float4*)(Bb + (size_t)br0 * N + bc0);
        float4 vb1 = *(const float4*)(Bb + (size_t)br1 * N + bc1);
        As[0][aseg0*4+0][arow0] = va0.x; As[0][aseg0*4+1][arow0] = va0.y;
        As[0][aseg0*4+2][arow0] = va0.z; As[0][aseg0*4+3][arow0] = va0.w;
        As[0][aseg1*4+0][arow1] = va1.x; As[0][aseg1*4+1][arow1] = va1.y;
        As[0][aseg1*4+2][arow1] = va1.z; As[0][aseg1*4+3][arow1] = va1.w;
        *(float4*)&Bs[0][br0][bc0] = vb0;
        *(float4*)&Bs[0][br1][bc1] = vb1;
    }
    __syncthreads();

    int cur = 0;
    for (int k0 = 0; k0 < K; k0 += 16) {
        const bool has_next = (k0 + 16) < K;
        float4 va0, va1, vb0, vb1;
        if (has_next) {                              // prefetch next tile -> regs
            int kn = k0 + 16;
            va0 = *(const float4*)(Ab + (size_t)arow0 * K + kn + aseg0 * 4);
            va1 = *(const float4*)(Ab + (size_t)arow1 * K + kn + aseg1 * 4);
            vb0 = *(const float4*)(Bb + (size_t)(kn + br0) * N + bc0);
            vb1 = *(const float4*)(Bb + (size_t)(kn + br1) * N + bc1);
        }
#pragma unroll
        for (int kk = 0; kk < 16; kk++) {            // compute from smem[cur]
            float4 a0 = *(const float4*)&As[cur][kk][ty*8];
            float4 a1 = *(const float4*)&As[cur][kk][ty*8+4];
            float4 b0 = *(const float4*)&Bs[cur][kk][tx*8];
            float4 b1 = *(const float4*)&Bs[cur][kk][tx*8+4];
            unsigned long long bp[4] = {pack2(b0.x,b0.y), pack2(b0.z,b0.w),
                                        pack2(b1.x,b1.y), pack2(b1.z,b1.w)};
            float av[8] = {a0.x,a0.y,a0.z,a0.w,a1.x,a1.y,a1.z,a1.w};
#pragma unroll
            for (int i = 0; i < 8; i++) {
                unsigned long long ap = pack2(av[i], av[i]);
#pragma unroll
                for (int j = 0; j < 4; j++) fma2(acc[i][j], ap, bp[j]);
            }
        }
        if (has_next) {                              // regs -> smem[cur^1]
            int nxt = cur ^ 1;
            As[nxt][aseg0*4+0][arow0] = va0.x; As[nxt][aseg0*4+1][arow0] = va0.y;
            As[nxt][aseg0*4+2][arow0] = va0.z; As[nxt][aseg0*4+3][arow0] = va0.w;
            As[nxt][aseg1*4+0][arow1] = va1.x; As[nxt][aseg1*4+1][arow1] = va1.y;
            As[nxt][aseg1*4+2][arow1] = va1.z; As[nxt][aseg1*4+3][arow1] = va1.w;
            *(float4*)&Bs[nxt][br0][bc0] = vb0;
            *(float4*)&Bs[nxt][br1][bc1] = vb1;
        }
        __syncthreads();
        cur ^= 1;
    }
#pragma unroll
    for (int i = 0; i < 8; i++) {
        int row = bm + ty*8 + i;
#pragma unroll
        for (int j = 0; j < 4; j++) {
            float2 v = unpack2(acc[i][j]);
            int col = bn + tx*8 + j*2;
            float2 o = make_float2(v.x + bias[col], v.y + bias[col+1]);
            *(float2*)&C[(size_t)row * N + col] = o;
        }
    }
}

// ======================================================================
// Batched NT GEMM + fused FMA-pipe exp epilogue, 2-stage pipelined:
// ep[z][q][k] = exp(SCALE * Q_z[q,:] . K_z[k,:])   (Kdim=64)
// ======================================================================
__global__ __launch_bounds__(256, 2)
void gemm_qk_exp(const float* __restrict__ qkv, float* __restrict__ ep)
{
    __shared__ float As[2][16][136];
    __shared__ float Bs[2][16][136];
    const int tid = threadIdx.x;
    const int z = blockIdx.z;
    const int b = z >> 4, h = z & 15;
    const int bm = blockIdx.y << 7, bn = blockIdx.x << 7;
    const int tx = tid & 15, ty = tid >> 4;

    const float* Aq = qkv + (size_t)b * 6291456 + h * 64;           // Q
    const float* Bk = qkv + (size_t)b * 6291456 + 1024 + h * 64;    // K
    float* C = ep + (size_t)z * 4194304;

    const int row0 = tid >> 2,          seg0 = tid & 3;
    const int row1 = (tid + 256) >> 2,  seg1 = tid & 3;

    unsigned long long acc[8][4];
#pragma unroll
    for (int i = 0; i < 8; i++)
#pragma unroll
        for (int j = 0; j < 4; j++) acc[i][j] = 0ull;

    // ---- prologue: tile 0 ----
    {
        float4 va0 = *(const float4*)(Aq + (size_t)(bm + row0) * 3072 + seg0 * 4);
        float4 va1 = *(const float4*)(Aq + (size_t)(bm + row1) * 3072 + seg1 * 4);
        float4 vb0 = *(const float4*)(Bk + (size_t)(bn + row0) * 3072 + seg0 * 4);
        float4 vb1 = *(const float4*)(Bk + (size_t)(bn + row1) * 3072 + seg1 * 4);
        As[0][seg0*4+0][row0] = va0.x; As[0][seg0*4+1][row0] = va0.y;
        As[0][seg0*4+2][row0] = va0.z; As[0][seg0*4+3][row0] = va0.w;
        As[0][seg1*4+0][row1] = va1.x; As[0][seg1*4+1][row1] = va1.y;
        As[0][seg1*4+2][row1] = va1.z; As[0][seg1*4+3][row1] = va1.w;
        Bs[0][seg0*4+0][row0] = vb0.x; Bs[0][seg0*4+1][row0] = vb0.y;
        Bs[0][seg0*4+2][row0] = vb0.z; Bs[0][seg0*4+3][row0] = vb0.w;
        Bs[0][seg1*4+0][row1] = vb1.x; Bs[0][seg1*4+1][row1] = vb1.y;
        Bs[0][seg1*4+2][row1] = vb1.z; Bs[0][seg1*4+3][row1] = vb1.w;
    }
    __syncthreads();

    int cur = 0;
    for (int k0 = 0; k0 < 64; k0 += 16) {
        const bool has_next = (k0 + 16) < 64;
        float4 va0, va1, vb0, vb1;
        if (has_next) {
            int kn = k0 + 16;
            va0 = *(const float4*)(Aq + (size_t)(bm + row0) * 3072 + kn + seg0 * 4);
            va1 = *(const float4*)(Aq + (size_t)(bm + row1) * 3072 + kn + seg1 * 4);
            vb0 = *(const float4*)(Bk + (size_t)(bn + row0) * 3072 + kn + seg0 * 4);
            vb1 = *(const float4*)(Bk + (size_t)(bn + row1) * 3072 + kn + seg1 * 4);
        }
#pragma unroll
        for (int kk = 0; kk < 16; kk++) {
            float4 a0 = *(const float4*)&As[cur][kk][ty*8];
            float4 a1 = *(const float4*)&As[cur][kk][ty*8+4];
            float4 b0 = *(const float4*)&Bs[cur][kk][tx*8];
            float4 b1 = *(const float4*)&Bs[cur][kk][tx*8+4];
            unsigned long long bp[4] = {pack2(b0.x,b0.y), pack2(b0.z,b0.w),
                                        pack2(b1.x,b1.y), pack2(b1.z,b1.w)};
            float av[8] = {a0.x,a0.y,a0.z,a0.w,a1.x,a1.y,a1.z,a1.w};
#pragma unroll
            for (int i = 0; i < 8; i++) {
                unsigned long long ap = pack2(av[i], av[i]);
#pragma unroll
                for (int j = 0; j < 4; j++) fma2(acc[i][j], ap, bp[j]);
            }
        }
        if (has_next) {
            int nxt = cur ^ 1;
            As[nxt][seg0*4+0][row0] = va0.x; As[nxt][seg0*4+1][row0] = va0.y;
            As[nxt][seg0*4+2][row0] = va0.z; As[nxt][seg0*4+3][row0] = va0.w;
            As[nxt][seg1*4+0][row1] = va1.x; As[nxt][seg1*4+1][row1] = va1.y;
            As[nxt][seg1*4+2][row1] = va1.z; As[nxt][seg1*4+3][row1] = va1.w;
            Bs[nxt][seg0*4+0][row0] = vb0.x; Bs[nxt][seg0*4+1][row0] = vb0.y;
            Bs[nxt][seg0*4+2][row0] = vb0.z; Bs[nxt][seg0*4+3][row0] = vb0.w;
            Bs[nxt][seg1*4+0][row1] = vb1.x; Bs[nxt][seg1*4+1][row1] = vb1.y;
            Bs[nxt][seg1*4+2][row1] = vb1.z; Bs[nxt][seg1*4+3][row1] = vb1.w;
        }
        __syncthreads();
        cur ^= 1;
    }
#pragma unroll
    for (int i = 0; i < 8; i++) {
        int row = bm + ty*8 + i;
#pragma unroll
        for (int j = 0; j < 4; j++) {
            float2 v = unpack2(acc[i][j]);
            int col = bn + tx*8 + j*2;
            float2 o = make_float2(fexp(v.x * SCALE), fexp(v.y * SCALE));
            __stcs((float2*)&C[(size_t)row * 2048 + col], o);
        }
    }
}

// ======================================================================
// zinv[b,q,k] = 1 / sum_h ep[b,h,q,k]   (softmax over HEADS axis)
// ======================================================================
__global__ __launch_bounds__(256)
void softmax_z(const float* __restrict__ ep, float* __restrict__ zinv)
{
    size_t i4 = (size_t)blockIdx.x * 256 + threadIdx.x;  // over 2*2048*2048/4
    size_t b = i4 >> 20;
    size_t qk4 = i4 & 1048575;
    const float4* p = (const float4*)(ep + (b << 26)) + qk4;
    float4 s = make_float4(0.f, 0.f, 0.f, 0.f);
#pragma unroll
    for (int h = 0; h < 16; h++) {
        float4 v = __ldcs(p + ((size_t)h << 20));
        s.x += v.x; s.y += v.y; s.z += v.z; s.w += v.w;
    }
    float4 o = make_float4(1.f/s.x, 1.f/s.y, 1.f/s.z, 1.f/s.w);
    *((float4*)zinv + i4) = o;
}

// ======================================================================
// Batched NN GEMM with normalization on A, 2-stage pipelined:
// wavg[b,q,h*64+d] = sum_k (ep[z,q,k]*zinv[b,q,k]) * V[b,k,h,d]
// BM=128, BN=64, BK=16, 256 threads, 8x4 microtile.
// ======================================================================
__global__ __launch_bounds__(256, 2)
void gemm_pv(const float* __restrict__ ep, const float* __restrict__ zinv,
             const float* __restrict__ qkv, float* __restrict__ wavg)
{
    __shared__ float As[2][16][136];
    __shared__ float Bs[2][16][64];
    const int tid = threadIdx.x;
    const int z = blockIdx.z, b = z >> 4, h = z & 15;
    const int bm = blockIdx.y << 7;
    const int tx = tid & 15, ty = tid >> 4;

    const float* A  = ep + (size_t)z * 4194304 + (size_t)bm * 2048;
    const float* Zi = zinv + (size_t)b * 4194304 + (size_t)bm * 2048;
    const float* Bv = qkv + (size_t)b * 6291456 + 2048 + h * 64;
    float* C = wavg + (size_t)b * 2097152 + h * 64;

    const int row0 = tid >> 2,          seg0 = tid & 3;
    const int row1 = (tid + 256) >> 2,  seg1 = tid & 3;
    const int vr = tid >> 4, vc = (tid & 15) << 2;   // V tile coords

    unsigned long long acc[8][2];
#pragma unroll
    for (int i = 0; i < 8; i++) { acc[i][0] = 0ull; acc[i][1] = 0ull; }

    // ---- prologue: tile 0 ----
    {
        size_t o0 = (size_t)row0 * 2048 + seg0 * 4;
        size_t o1 = (size_t)row1 * 2048 + seg1 * 4;
        float4 a0 = __ldcs((const float4*)(A + o0));
        float4 a1 = __ldcs((const float4*)(A + o1));
        float4 z0 = *(const float4*)(Zi + o0);
        float4 z1 = *(const float4*)(Zi + o1);
        float4 vv = *(const float4*)(Bv + (size_t)vr * 3072 + vc);
        As[0][seg0*4+0][row0] = a0.x * z0.x; As[0][seg0*4+1][row0] = a0.y * z0.y;
        As[0][seg0*4+2][row0] = a0.z * z0.z; As[0][seg0*4+3][row0] = a0.w * z0.w;
        As[0][seg1*4+0][row1] = a1.x * z1.x; As[0][seg1*4+1][row1] = a1.y * z1.y;
        As[0][seg1*4+2][row1] = a1.z * z1.z; As[0][seg1*4+3][row1] = a1.w * z1.w;
        *(float4*)&Bs[0][vr][vc] = vv;
    }
    __syncthreads();

    int cur = 0;
    for (int k0 = 0; k0 < 2048; k0 += 16) {
        const bool has_next = (k0 + 16) < 2048;
        float4 a0, a1, z0, z1, vv;
        if (has_next) {
            int kn = k0 + 16;
            size_t o0 = (size_t)row0 * 2048 + kn + seg0 * 4;
            size_t o1 = (size_t)row1 * 2048 + kn + seg1 * 4;
            a0 = __ldcs((const float4*)(A + o0));
            a1 = __ldcs((const float4*)(A + o1));
            z0 = *(const float4*)(Zi + o0);
            z1 = *(const float4*)(Zi + o1);
            vv = *(const float4*)(Bv + (size_t)(kn + vr) * 3072 + vc);
        }
#pragma unroll
        for (int kk = 0; kk < 16; kk++) {
            float4 va0 = *(const float4*)&As[cur][kk][ty*8];
            float4 va1 = *(const float4*)&As[cur][kk][ty*8+4];
            float4 vb0 = *(const float4*)&Bs[cur][kk][tx*4];
            unsigned long long bp[2] = {pack2(vb0.x,vb0.y), pack2(vb0.z,vb0.w)};
            float av[8] = {va0.x,va0.y,va0.z,va0.w,va1.x,va1.y,va1.z,va1.w};
#pragma unroll
            for (int i = 0; i < 8; i++) {
                unsigned long long ap = pack2(av[i], av[i]);
                fma2(acc[i][0], ap, bp[0]);
                fma2(acc[i][1], ap, bp[1]);
            }
        }
        if (has_next) {
            int nxt = cur ^ 1;
            As[nxt][seg0*4+0][row0] = a0.x * z0.x; As[nxt][seg0*4+1][row0] = a0.y * z0.y;
            As[nxt][seg0*4+2][row0] = a0.z * z0.z; As[nxt][seg0*4+3][row0] = a0.w * z0.w;
            As[nxt][seg1*4+0][row1] = a1.x * z1.x; As[nxt][seg1*4+1][row1] = a1.y * z1.y;
            As[nxt][seg1*4+2][row1] = a1.z * z1.z; As[nxt][seg1*4+3][row1] = a1.w * z1.w;
            *(float4*)&Bs[nxt][vr][vc] = vv;
        }
        __syncthreads();
        cur ^= 1;
    }
#pragma unroll
    for (int i = 0; i < 8; i++) {
        int row = bm + ty*8 + i;
#pragma unroll
        for (int j = 0; j < 2; j++) {
            float2 v = unpack2(acc[i][j]);
            *(float2*)&C[(size_t)row * 1024 + tx*4 + j*2] = v;
        }
    }
}

// ======================================================================
extern "C" void kernel_launch(void* const* d_in, const int* in_sizes, int n_in,
                              void* d_out, int out_size)
{
    const float* x      = (const float*)d_in[0];   // (2,2048,1024)
    const float* w_qkv  = (const float*)d_in[1];   // (1024,3072)
    const float* b_qkv  = (const float*)d_in[2];   // (3072,)
    const float* w_proj = (const float*)d_in[3];   // (1024,1024)
    const float* b_proj = (const float*)d_in[4];   // (1024,)
    float* out = (float*)d_out;                    // (2,2048,1024)

    float *qkv, *ep, *zinv, *wavg;
    cudaGetSymbolAddress((void**)&qkv,  g_qkv);
    cudaGetSymbolAddress((void**)&ep,   g_ep);
    cudaGetSymbolAddress((void**)&zinv, g_zinv);
    cudaGetSymbolAddress((void**)&wavg, g_wavg);

    // 1) qkv = x @ w_qkv + b_qkv          (M=4096, N=3072, K=1024)
    gemm_nn_bias<<<dim3(24, 32), 256>>>(x, w_qkv, b_qkv, qkv, 4096, 3072, 1024);
    // 2) ep[b,h,q,k] = exp(SCALE * q.k)   (32 batches of 2048x2048x64, FMA-exp fused)
    gemm_qk_exp<<<dim3(16, 16, 32), 256>>>(qkv, ep);
    // 3) zinv = 1 / sum_h ep              (softmax denominator over heads)
    softmax_z<<<8192, 256>>>(ep, zinv);
    // 4) wavg = (ep*zinv) @ V             (32 batches of 2048x64x2048)
    gemm_pv<<<dim3(1, 16, 32), 256>>>(ep, zinv, qkv, wavg);
    // 5) out = wavg @ w_proj + b_proj     (M=4096, N=1024, K=1024)
    gemm_nn_bias<<<dim3(8, 32), 256>>>(wavg, w_proj, b_proj, out, 4096, 1024, 1024);
}